// round 1
// baseline (speedup 1.0000x reference)
#include <cuda_runtime.h>
#include <math.h>

#define DD 768
#define MM 8192
#define CC 2048
#define LL 16

// Per-mention score scratch: s[m] = sum_n relu((X W1)[m,n] + b1[n]) * Wout[n]
__device__ float g_s[MM];

__global__ void zero_s_kernel() {
    int i = blockIdx.x * 256 + threadIdx.x;
    if (i < MM) g_s[i] = 0.0f;
}

// ---------------- fused score GEMM ----------------
#define BM 128
#define BN 128
#define BK 16
#define APAD 4

__device__ __forceinline__ unsigned long long pack2(float lo, float hi) {
    unsigned long long r;
    asm("mov.b64 %0, {%1, %2};" : "=l"(r) : "f"(lo), "f"(hi));
    return r;
}
__device__ __forceinline__ void unpack2(unsigned long long v, float& lo, float& hi) {
    asm("mov.b64 {%0, %1}, %2;" : "=f"(lo), "=f"(hi) : "l"(v));
}
__device__ __forceinline__ void ffma2(unsigned long long& d, unsigned long long a, unsigned long long b) {
    asm("fma.rn.f32x2 %0, %1, %2, %0;" : "+l"(d) : "l"(a), "l"(b));
}

__global__ __launch_bounds__(256) void score_gemm_kernel(
    const float* __restrict__ X,      // [MM, DD]
    const float* __restrict__ W1,     // [DD, DD]
    const float* __restrict__ b1,     // [DD]
    const float* __restrict__ Wout    // [DD]
) {
    __shared__ float As[BK][BM + APAD];   // transposed A tile
    __shared__ float Bs[BK][BN];

    const int tid = threadIdx.x;
    const int tx = tid & 15;          // col group: 8 cols each
    const int ty = tid >> 4;          // row group: 8 rows each
    const int m0 = blockIdx.y * BM;
    const int n0 = blockIdx.x * BN;

    // acc[i][j] holds rows (ty*8 + 2i, ty*8 + 2i + 1), col (tx*8 + j), packed f32x2
    unsigned long long acc[4][8];
#pragma unroll
    for (int i = 0; i < 4; i++)
#pragma unroll
        for (int j = 0; j < 8; j++) acc[i][j] = 0ULL;

    for (int k0 = 0; k0 < DD; k0 += BK) {
        // load A tile 128x16 -> transposed As[k][m]
#pragma unroll
        for (int it = 0; it < 2; it++) {
            int id = tid + it * 256;          // 0..511
            int ar = id >> 2;                 // 0..127
            int ac = (id & 3) * 4;            // 0,4,8,12
            float4 v = *(const float4*)(X + (size_t)(m0 + ar) * DD + k0 + ac);
            As[ac + 0][ar] = v.x;
            As[ac + 1][ar] = v.y;
            As[ac + 2][ar] = v.z;
            As[ac + 3][ar] = v.w;
        }
        // load B tile 16x128
#pragma unroll
        for (int it = 0; it < 2; it++) {
            int id = tid + it * 256;          // 0..511
            int kr = id >> 5;                 // 0..15
            int nc = (id & 31) * 4;           // 0..124
            *(float4*)&Bs[kr][nc] = *(const float4*)(W1 + (size_t)(k0 + kr) * DD + n0 + nc);
        }
        __syncthreads();

#pragma unroll
        for (int kk = 0; kk < BK; kk++) {
            const unsigned long long* ap =
                (const unsigned long long*)&As[kk][ty * 8];  // 4 row-pairs, contiguous
            unsigned long long pa[4];
#pragma unroll
            for (int i = 0; i < 4; i++) pa[i] = ap[i];

            float4 bl = *(const float4*)&Bs[kk][tx * 8];
            float4 bh = *(const float4*)&Bs[kk][tx * 8 + 4];
            unsigned long long pb[8];
            pb[0] = pack2(bl.x, bl.x); pb[1] = pack2(bl.y, bl.y);
            pb[2] = pack2(bl.z, bl.z); pb[3] = pack2(bl.w, bl.w);
            pb[4] = pack2(bh.x, bh.x); pb[5] = pack2(bh.y, bh.y);
            pb[6] = pack2(bh.z, bh.z); pb[7] = pack2(bh.w, bh.w);

#pragma unroll
            for (int i = 0; i < 4; i++)
#pragma unroll
                for (int j = 0; j < 8; j++) ffma2(acc[i][j], pa[i], pb[j]);
        }
        __syncthreads();
    }

    // epilogue: bias + relu + dot with Wout, reduce over cols, atomic into g_s
    float bj[8], wj[8];
#pragma unroll
    for (int j = 0; j < 8; j++) {
        bj[j] = b1[n0 + tx * 8 + j];
        wj[j] = Wout[n0 + tx * 8 + j];
    }
    float part[8];
#pragma unroll
    for (int i = 0; i < 4; i++) {
        float plo = 0.0f, phi = 0.0f;
#pragma unroll
        for (int j = 0; j < 8; j++) {
            float lo, hi;
            unpack2(acc[i][j], lo, hi);
            lo = fmaxf(lo + bj[j], 0.0f);
            hi = fmaxf(hi + bj[j], 0.0f);
            plo += lo * wj[j];
            phi += hi * wj[j];
        }
        part[2 * i]     = plo;
        part[2 * i + 1] = phi;
    }
#pragma unroll
    for (int r = 0; r < 8; r++) {
        float v = part[r];
        v += __shfl_down_sync(0xffffffffu, v, 8, 16);
        v += __shfl_down_sync(0xffffffffu, v, 4, 16);
        v += __shfl_down_sync(0xffffffffu, v, 2, 16);
        v += __shfl_down_sync(0xffffffffu, v, 1, 16);
        if (tx == 0) atomicAdd(&g_s[m0 + ty * 8 + r], v);
    }
}

// ---------------- softmax + weighted aggregation ----------------
__global__ __launch_bounds__(256) void softmax_agg_kernel(
    const float* __restrict__ X,        // [MM, DD]
    const int* __restrict__ cidx,       // [CC, LL]
    const int* __restrict__ clen,       // [CC]
    float* __restrict__ out             // [CC, DD]
) {
    __shared__ float sc[LL];
    __shared__ int ix[LL];
    const int c = blockIdx.x;
    const int tid = threadIdx.x;

    if (tid < LL) {
        int len = clen[c];
        int id = cidx[c * LL + tid];
        ix[tid] = id;
        sc[tid] = (tid < len) ? g_s[id] : -INFINITY;
    }
    __syncthreads();

    float mx = -INFINITY;
#pragma unroll
    for (int l = 0; l < LL; l++) mx = fmaxf(mx, sc[l]);
    float p[LL];
    float sum = 0.0f;
#pragma unroll
    for (int l = 0; l < LL; l++) {
        p[l] = __expf(sc[l] - mx);   // masked slots: exp(-inf) = 0
        sum += p[l];
    }
    float inv = 1.0f / sum;
#pragma unroll
    for (int l = 0; l < LL; l++) p[l] *= inv;

    for (int d = tid; d < DD; d += blockDim.x) {
        float acc = 0.0f;
#pragma unroll
        for (int l = 0; l < LL; l++)
            acc += p[l] * X[(size_t)ix[l] * DD + d];
        out[(size_t)c * DD + d] = acc;
    }
}

extern "C" void kernel_launch(void* const* d_in, const int* in_sizes, int n_in,
                              void* d_out, int out_size) {
    const float* X    = (const float*)d_in[0];   // mention_vectors [1,8192,768]
    const int*   cidx = (const int*)d_in[1];     // concept_indices [2048,16]
    const int*   clen = (const int*)d_in[2];     // concept_lengths [2048]
    const float* W1   = (const float*)d_in[3];   // [768,768]
    const float* b1   = (const float*)d_in[4];   // [768]
    const float* Wout = (const float*)d_in[5];   // [768]
    // d_in[6] = bout: softmax-invariant, unused
    float* out = (float*)d_out;                  // [1,2048,768]

    zero_s_kernel<<<MM / 256, 256>>>();
    dim3 grid(DD / BN, MM / BM);                 // (6, 64) = 384 blocks
    score_gemm_kernel<<<grid, 256>>>(X, W1, b1, Wout);
    softmax_agg_kernel<<<CC, 256>>>(X, cidx, clen, out);
}

// round 3
// speedup vs baseline: 1.8212x; 1.8212x over previous
#include <cuda_runtime.h>
#include <cuda_bf16.h>
#include <cstdint>
#include <math.h>

#define DD 768
#define MM 8192
#define CC 2048
#define LL 16

#define BM 128
#define BN 128
#define BK 32
#define NITER (DD / BK)       // 24

// padded smem row: 32 + 8 elements = 80 bytes (conflict-free for ldmatrix)
#define LDT 40
#define MAT_BYTES (128 * LDT * 2)      // 10240 per matrix (128 rows)
#define OFF_AH 0
#define OFF_AL (1 * MAT_BYTES)
#define OFF_BH (2 * MAT_BYTES)
#define OFF_BL (3 * MAT_BYTES)
#define STAGE_BYTES (4 * MAT_BYTES)    // 40960
#define SMEM_TOTAL (2 * STAGE_BYTES)   // 81920

// ---------------- device globals (no allocs allowed) ----------------
__device__ float g_s[MM];
__device__ __nv_bfloat16 g_Xhi[MM * DD];
__device__ __nv_bfloat16 g_Xlo[MM * DD];
__device__ __nv_bfloat16 g_Bhi[DD * DD];   // [n][k] = W1[k][n] (transposed, K-major)
__device__ __nv_bfloat16 g_Blo[DD * DD];

// ---------------- helpers ----------------
__device__ __forceinline__ uint32_t smem_u32(const void* p) {
    uint32_t a;
    asm("{ .reg .u64 t; cvta.to.shared.u64 t, %1; cvt.u32.u64 %0, t; }" : "=r"(a) : "l"(p));
    return a;
}
__device__ __forceinline__ void cp16(uint32_t dst, const void* src) {
    asm volatile("cp.async.cg.shared.global [%0], [%1], 16;" :: "r"(dst), "l"(src));
}
__device__ __forceinline__ void ldsm4(uint32_t* r, uint32_t addr) {
    asm volatile("ldmatrix.sync.aligned.m8n8.x4.shared.b16 {%0,%1,%2,%3}, [%4];"
                 : "=r"(r[0]), "=r"(r[1]), "=r"(r[2]), "=r"(r[3]) : "r"(addr));
}
__device__ __forceinline__ void mma16816(float* c, const uint32_t* a, const uint32_t* b) {
    asm volatile(
        "mma.sync.aligned.m16n8k16.row.col.f32.bf16.bf16.f32 "
        "{%0,%1,%2,%3}, {%4,%5,%6,%7}, {%8,%9}, {%0,%1,%2,%3};"
        : "+f"(c[0]), "+f"(c[1]), "+f"(c[2]), "+f"(c[3])
        : "r"(a[0]), "r"(a[1]), "r"(a[2]), "r"(a[3]), "r"(b[0]), "r"(b[1]));
}

// ---------------- precompute kernels ----------------
__global__ void zero_s_kernel() {
    int i = blockIdx.x * 256 + threadIdx.x;
    if (i < MM) g_s[i] = 0.0f;
}

__global__ void convert_X_kernel(const float* __restrict__ X) {
    int i = blockIdx.x * 256 + threadIdx.x;     // over MM*DD/4
    float4 v = ((const float4*)X)[i];
    float xs[4] = {v.x, v.y, v.z, v.w};
    __nv_bfloat16 h[4], l[4];
#pragma unroll
    for (int j = 0; j < 4; j++) {
        h[j] = __float2bfloat16(xs[j]);
        l[j] = __float2bfloat16(xs[j] - __bfloat162float(h[j]));
    }
    uint2 ph, pl;
    ph.x = ((uint32_t)*(uint16_t*)&h[1] << 16) | *(uint16_t*)&h[0];
    ph.y = ((uint32_t)*(uint16_t*)&h[3] << 16) | *(uint16_t*)&h[2];
    pl.x = ((uint32_t)*(uint16_t*)&l[1] << 16) | *(uint16_t*)&l[0];
    pl.y = ((uint32_t)*(uint16_t*)&l[3] << 16) | *(uint16_t*)&l[2];
    ((uint2*)g_Xhi)[i] = ph;
    ((uint2*)g_Xlo)[i] = pl;
}

__global__ void convert_W1_kernel(const float* __restrict__ W1) {
    __shared__ float t[32][33];
    int n0 = blockIdx.x * 32, k0 = blockIdx.y * 32;
    int tx = threadIdx.x, ty = threadIdx.y;     // (32, 8)
#pragma unroll
    for (int i = 0; i < 32; i += 8)
        t[ty + i][tx] = W1[(size_t)(k0 + ty + i) * DD + n0 + tx];
    __syncthreads();
#pragma unroll
    for (int i = 0; i < 32; i += 8) {
        float x = t[tx][ty + i];
        __nv_bfloat16 h = __float2bfloat16(x);
        __nv_bfloat16 l = __float2bfloat16(x - __bfloat162float(h));
        size_t o = (size_t)(n0 + ty + i) * DD + k0 + tx;
        g_Bhi[o] = h;
        g_Blo[o] = l;
    }
}

// ---------------- mma.sync score GEMM ----------------
__device__ __forceinline__ void load_stage(uint32_t sbase, int k0, int m0, int n0, int tid) {
    int r = tid >> 2;                 // 0..31
    int cb = tid & 3;                 // 16B block within 64B row chunk
    uint32_t so = (uint32_t)r * (LDT * 2) + cb * 16;
    size_t goA = (size_t)(m0 + r) * DD + k0 + cb * 8;
    size_t goB = (size_t)(n0 + r) * DD + k0 + cb * 8;
#pragma unroll
    for (int mb = 0; mb < 4; mb++) {
        uint32_t s = so + mb * (32 * LDT * 2);
        size_t ga = goA + (size_t)mb * 32 * DD;
        size_t gb = goB + (size_t)mb * 32 * DD;
        cp16(sbase + OFF_AH + s, g_Xhi + ga);
        cp16(sbase + OFF_AL + s, g_Xlo + ga);
        cp16(sbase + OFF_BH + s, g_Bhi + gb);
        cp16(sbase + OFF_BL + s, g_Blo + gb);
    }
    asm volatile("cp.async.commit_group;" ::: "memory");
}

__global__ __launch_bounds__(128, 2) void score_gemm_mma(
    const float* __restrict__ b1, const float* __restrict__ Wout) {
    extern __shared__ char smem[];
    uint32_t sb = smem_u32(smem);
    const int tid = threadIdx.x;
    const int wid = tid >> 5, lane = tid & 31;
    const int wm = (wid >> 1) * 64;           // warp m offset in tile
    const int wn = (wid & 1) * 64;            // warp n offset in tile
    const int m0 = blockIdx.y * BM, n0 = blockIdx.x * BN;

    float acc[4][8][4];
#pragma unroll
    for (int mt = 0; mt < 4; mt++)
#pragma unroll
        for (int nt = 0; nt < 8; nt++)
#pragma unroll
            for (int c = 0; c < 4; c++) acc[mt][nt][c] = 0.0f;

    // prologue: 2 stages in flight
    load_stage(sb, 0, m0, n0, tid);
    load_stage(sb + STAGE_BYTES, BK, m0, n0, tid);

    // precomputed ldmatrix lane offsets (bytes)
    const uint32_t aRow = (lane & 15);
    const uint32_t aCol = (lane >> 4) << 3;
    const uint32_t bN   = ((lane >> 4) << 3) + (lane & 7);
    const uint32_t bK   = ((lane >> 3) & 1) << 3;

    for (int it = 0; it < NITER; it++) {
        asm volatile("cp.async.wait_group 1;" ::: "memory");
        __syncthreads();
        uint32_t st = sb + (it & 1) * STAGE_BYTES;

#pragma unroll
        for (int kk = 0; kk < BK; kk += 16) {
            uint32_t Ah[4][4], Al[4][4], Bh[4][4], Bl[4][4];
#pragma unroll
            for (int mt = 0; mt < 4; mt++) {
                uint32_t off = ((wm + mt * 16 + aRow) * LDT + kk + aCol) * 2;
                ldsm4(Ah[mt], st + OFF_AH + off);
            }
#pragma unroll
            for (int np = 0; np < 4; np++) {
                uint32_t off = ((wn + np * 16 + bN) * LDT + kk + bK) * 2;
                ldsm4(Bh[np], st + OFF_BH + off);
            }
            // combo 1: Ahi * Bhi
#pragma unroll
            for (int mt = 0; mt < 4; mt++)
#pragma unroll
                for (int np = 0; np < 4; np++) {
                    mma16816(acc[mt][2 * np],     Ah[mt], Bh[np]);
                    mma16816(acc[mt][2 * np + 1], Ah[mt], Bh[np] + 2);
                }
            // combo 2: Ahi * Blo
#pragma unroll
            for (int np = 0; np < 4; np++) {
                uint32_t off = ((wn + np * 16 + bN) * LDT + kk + bK) * 2;
                ldsm4(Bl[np], st + OFF_BL + off);
            }
#pragma unroll
            for (int mt = 0; mt < 4; mt++)
#pragma unroll
                for (int np = 0; np < 4; np++) {
                    mma16816(acc[mt][2 * np],     Ah[mt], Bl[np]);
                    mma16816(acc[mt][2 * np + 1], Ah[mt], Bl[np] + 2);
                }
            // combo 3: Alo * Bhi
#pragma unroll
            for (int mt = 0; mt < 4; mt++) {
                uint32_t off = ((wm + mt * 16 + aRow) * LDT + kk + aCol) * 2;
                ldsm4(Al[mt], st + OFF_AL + off);
            }
#pragma unroll
            for (int mt = 0; mt < 4; mt++)
#pragma unroll
                for (int np = 0; np < 4; np++) {
                    mma16816(acc[mt][2 * np],     Al[mt], Bh[np]);
                    mma16816(acc[mt][2 * np + 1], Al[mt], Bh[np] + 2);
                }
        }
        __syncthreads();
        if (it + 2 < NITER)
            load_stage(st, (it + 2) * BK, m0, n0, tid);
    }

    // epilogue: bias + relu + dot(Wout), quad-reduce, atomic per-mention score
    const int qr = lane >> 2;      // row within 8
    const int qc = lane & 3;
#pragma unroll
    for (int mt = 0; mt < 4; mt++) {
        float r0 = 0.0f, r1 = 0.0f;
#pragma unroll
        for (int nt = 0; nt < 8; nt++) {
            int n = n0 + wn + nt * 8 + qc * 2;
            float w0 = Wout[n], w1 = Wout[n + 1];
            float bb0 = b1[n], bb1 = b1[n + 1];
            r0 += fmaxf(acc[mt][nt][0] + bb0, 0.0f) * w0 +
                  fmaxf(acc[mt][nt][1] + bb1, 0.0f) * w1;
            r1 += fmaxf(acc[mt][nt][2] + bb0, 0.0f) * w0 +
                  fmaxf(acc[mt][nt][3] + bb1, 0.0f) * w1;
        }
        r0 += __shfl_xor_sync(0xffffffffu, r0, 1);
        r0 += __shfl_xor_sync(0xffffffffu, r0, 2);
        r1 += __shfl_xor_sync(0xffffffffu, r1, 1);
        r1 += __shfl_xor_sync(0xffffffffu, r1, 2);
        if (qc == 0) {
            atomicAdd(&g_s[m0 + wm + mt * 16 + qr], r0);
            atomicAdd(&g_s[m0 + wm + mt * 16 + qr + 8], r1);
        }
    }
}

// ---------------- softmax + weighted aggregation ----------------
__global__ __launch_bounds__(256) void softmax_agg_kernel(
    const float* __restrict__ X, const int* __restrict__ cidx,
    const int* __restrict__ clen, float* __restrict__ out) {
    __shared__ float sc[LL];
    __shared__ int ix[LL];
    const int c = blockIdx.x;
    const int tid = threadIdx.x;

    if (tid < LL) {
        int len = clen[c];
        int id = cidx[c * LL + tid];
        ix[tid] = id;
        sc[tid] = (tid < len) ? g_s[id] : -INFINITY;
    }
    __syncthreads();

    float mx = -INFINITY;
#pragma unroll
    for (int l = 0; l < LL; l++) mx = fmaxf(mx, sc[l]);
    float p[LL];
    float sum = 0.0f;
#pragma unroll
    for (int l = 0; l < LL; l++) { p[l] = __expf(sc[l] - mx); sum += p[l]; }
    float inv = 1.0f / sum;
#pragma unroll
    for (int l = 0; l < LL; l++) p[l] *= inv;

    for (int d = tid; d < DD; d += blockDim.x) {
        float acc = 0.0f;
#pragma unroll
        for (int l = 0; l < LL; l++)
            acc += p[l] * X[(size_t)ix[l] * DD + d];
        out[(size_t)c * DD + d] = acc;
    }
}

extern "C" void kernel_launch(void* const* d_in, const int* in_sizes, int n_in,
                              void* d_out, int out_size) {
    const float* X    = (const float*)d_in[0];
    const int*   cidx = (const int*)d_in[1];
    const int*   clen = (const int*)d_in[2];
    const float* W1   = (const float*)d_in[3];
    const float* b1   = (const float*)d_in[4];
    const float* Wout = (const float*)d_in[5];
    float* out = (float*)d_out;

    cudaFuncSetAttribute(score_gemm_mma, cudaFuncAttributeMaxDynamicSharedMemorySize,
                         SMEM_TOTAL);

    zero_s_kernel<<<MM / 256, 256>>>();
    convert_X_kernel<<<MM * DD / 4 / 256, 256>>>(X);
    convert_W1_kernel<<<dim3(DD / 32, DD / 32), dim3(32, 8)>>>(W1);
    score_gemm_mma<<<dim3(DD / BN, MM / BM), 128, SMEM_TOTAL>>>(b1, Wout);
    softmax_agg_kernel<<<CC, 256>>>(X, cidx, clen, out);
}

// round 4
// speedup vs baseline: 3.2154x; 1.7655x over previous
#include <cuda_runtime.h>
#include <cuda_fp16.h>
#include <cstdint>
#include <math.h>

#define DD 768
#define MM 8192
#define CC 2048
#define LL 16

#define BM 64
#define BN 128
#define BK 32
#define NITER (DD / BK)       // 24
#define NSTAGE 3

// padded smem row: 32 data + 8 pad fp16 = 80B (conflict-free ldmatrix)
#define LDT 40
#define OFF_AH 0
#define OFF_AL (BM * LDT * 2)              // 5120
#define OFF_BH (2 * BM * LDT * 2)          // 10240
#define STAGE_BYTES (OFF_BH + BN * LDT * 2) // 20480
#define SMEM_TOTAL (NSTAGE * STAGE_BYTES)   // 61440

// ---------------- device globals ----------------
__device__ float g_s[MM];
__device__ __half g_Xh[MM * DD];
__device__ __half g_Xl[MM * DD];
__device__ __half g_Bh[DD * DD];   // [n][k] = W1[k][n] (transposed, K-major)

// ---------------- helpers ----------------
__device__ __forceinline__ uint32_t smem_u32(const void* p) {
    uint32_t a;
    asm("{ .reg .u64 t; cvta.to.shared.u64 t, %1; cvt.u32.u64 %0, t; }" : "=r"(a) : "l"(p));
    return a;
}
__device__ __forceinline__ void cp16(uint32_t dst, const void* src) {
    asm volatile("cp.async.cg.shared.global [%0], [%1], 16;" :: "r"(dst), "l"(src));
}
__device__ __forceinline__ void ldsm4(uint32_t* r, uint32_t addr) {
    asm volatile("ldmatrix.sync.aligned.m8n8.x4.shared.b16 {%0,%1,%2,%3}, [%4];"
                 : "=r"(r[0]), "=r"(r[1]), "=r"(r[2]), "=r"(r[3]) : "r"(addr));
}
__device__ __forceinline__ void mma16816(float* c, const uint32_t* a, const uint32_t* b) {
    asm volatile(
        "mma.sync.aligned.m16n8k16.row.col.f32.f16.f16.f32 "
        "{%0,%1,%2,%3}, {%4,%5,%6,%7}, {%8,%9}, {%0,%1,%2,%3};"
        : "+f"(c[0]), "+f"(c[1]), "+f"(c[2]), "+f"(c[3])
        : "r"(a[0]), "r"(a[1]), "r"(a[2]), "r"(a[3]), "r"(b[0]), "r"(b[1]));
}

// ---------------- precompute kernels ----------------
__global__ void convert_X_kernel(const float* __restrict__ X) {
    int i = blockIdx.x * 256 + threadIdx.x;     // over MM*DD/4
    if (i < MM) g_s[i] = 0.0f;                  // fold zero_s in here
    float4 v = ((const float4*)X)[i];
    float xs[4] = {v.x, v.y, v.z, v.w};
    __half h[4], l[4];
#pragma unroll
    for (int j = 0; j < 4; j++) {
        h[j] = __float2half_rn(xs[j]);
        l[j] = __float2half_rn(xs[j] - __half2float(h[j]));
    }
    uint2 ph, pl;
    ph.x = ((uint32_t)*(uint16_t*)&h[1] << 16) | *(uint16_t*)&h[0];
    ph.y = ((uint32_t)*(uint16_t*)&h[3] << 16) | *(uint16_t*)&h[2];
    pl.x = ((uint32_t)*(uint16_t*)&l[1] << 16) | *(uint16_t*)&l[0];
    pl.y = ((uint32_t)*(uint16_t*)&l[3] << 16) | *(uint16_t*)&l[2];
    ((uint2*)g_Xh)[i] = ph;
    ((uint2*)g_Xl)[i] = pl;
}

__global__ void convert_W1_kernel(const float* __restrict__ W1) {
    __shared__ float t[32][33];
    int n0 = blockIdx.x * 32, k0 = blockIdx.y * 32;
    int tx = threadIdx.x, ty = threadIdx.y;     // (32, 8)
#pragma unroll
    for (int i = 0; i < 32; i += 8)
        t[ty + i][tx] = W1[(size_t)(k0 + ty + i) * DD + n0 + tx];
    __syncthreads();
#pragma unroll
    for (int i = 0; i < 32; i += 8)
        g_Bh[(size_t)(n0 + ty + i) * DD + k0 + tx] = __float2half_rn(t[tx][ty + i]);
}

// ---------------- mma.sync score GEMM ----------------
__device__ __forceinline__ void load_stage(uint32_t base, int k0, int m0, int n0, int tid) {
    int r = tid >> 2;                 // 0..31
    int cb = tid & 3;                 // 16B block (8 fp16) within 64B row
#pragma unroll
    for (int p = 0; p < 2; p++) {     // A hi+lo: 64 rows
        int row = p * 32 + r;
        uint32_t so = (uint32_t)row * (LDT * 2) + cb * 16;
        size_t g = (size_t)(m0 + row) * DD + k0 + cb * 8;
        cp16(base + OFF_AH + so, g_Xh + g);
        cp16(base + OFF_AL + so, g_Xl + g);
    }
#pragma unroll
    for (int p = 0; p < 4; p++) {     // B: 128 rows
        int row = p * 32 + r;
        uint32_t so = (uint32_t)row * (LDT * 2) + cb * 16;
        cp16(base + OFF_BH + so, g_Bh + (size_t)(n0 + row) * DD + k0 + cb * 8);
    }
    asm volatile("cp.async.commit_group;" ::: "memory");
}

__global__ __launch_bounds__(128, 3) void score_gemm_mma(
    const float* __restrict__ b1, const float* __restrict__ Wout) {
    extern __shared__ char smem[];
    uint32_t sb = smem_u32(smem);
    const int tid = threadIdx.x;
    const int wid = tid >> 5, lane = tid & 31;
    const int wm = (wid >> 1) * 32;           // warp m offset (0/32)
    const int wn = (wid & 1) * 64;            // warp n offset (0/64)
    const int m0 = blockIdx.y * BM, n0 = blockIdx.x * BN;

    float acc[2][8][4];
#pragma unroll
    for (int mt = 0; mt < 2; mt++)
#pragma unroll
        for (int nt = 0; nt < 8; nt++)
#pragma unroll
            for (int c = 0; c < 4; c++) acc[mt][nt][c] = 0.0f;

    // prologue: 2 stages in flight
    load_stage(sb, 0, m0, n0, tid);
    load_stage(sb + STAGE_BYTES, BK, m0, n0, tid);

    // ldmatrix lane offsets
    const uint32_t aRow = (lane & 15);
    const uint32_t aCol = (lane >> 4) << 3;
    const uint32_t bN   = ((lane >> 4) << 3) + (lane & 7);
    const uint32_t bK   = ((lane >> 3) & 1) << 3;

    for (int it = 0; it < NITER; it++) {
        if (it + 1 < NITER) asm volatile("cp.async.wait_group 1;" ::: "memory");
        else                asm volatile("cp.async.wait_group 0;" ::: "memory");
        __syncthreads();
        uint32_t st = sb + (it % NSTAGE) * STAGE_BYTES;
        if (it + 2 < NITER)
            load_stage(sb + ((it + 2) % NSTAGE) * STAGE_BYTES, (it + 2) * BK, m0, n0, tid);

        // load ALL frags for this BK=32 iter, then run 64 back-to-back MMAs
        uint32_t Ah[2][2][4], Al[2][2][4], Bh[2][4][4];
#pragma unroll
        for (int h = 0; h < 2; h++) {
            int kk = h * 16;
#pragma unroll
            for (int mt = 0; mt < 2; mt++) {
                uint32_t off = ((wm + mt * 16 + aRow) * LDT + kk + aCol) * 2;
                ldsm4(Ah[h][mt], st + OFF_AH + off);
                ldsm4(Al[h][mt], st + OFF_AL + off);
            }
#pragma unroll
            for (int np = 0; np < 4; np++) {
                uint32_t off = ((wn + np * 16 + bN) * LDT + kk + bK) * 2;
                ldsm4(Bh[h][np], st + OFF_BH + off);
            }
        }
#pragma unroll
        for (int h = 0; h < 2; h++)
#pragma unroll
            for (int mt = 0; mt < 2; mt++)
#pragma unroll
                for (int np = 0; np < 4; np++) {
                    mma16816(acc[mt][2 * np],     Ah[h][mt], Bh[h][np]);
                    mma16816(acc[mt][2 * np + 1], Ah[h][mt], Bh[h][np] + 2);
                    mma16816(acc[mt][2 * np],     Al[h][mt], Bh[h][np]);
                    mma16816(acc[mt][2 * np + 1], Al[h][mt], Bh[h][np] + 2);
                }
    }

    // epilogue: bias + relu + dot(Wout), quad-reduce, atomic per-mention score
    const int qr = lane >> 2;
    const int qc = lane & 3;
#pragma unroll
    for (int mt = 0; mt < 2; mt++) {
        float r0 = 0.0f, r1 = 0.0f;
#pragma unroll
        for (int nt = 0; nt < 8; nt++) {
            int n = n0 + wn + nt * 8 + qc * 2;
            float w0 = Wout[n], w1 = Wout[n + 1];
            float bb0 = b1[n], bb1 = b1[n + 1];
            r0 += fmaxf(acc[mt][nt][0] + bb0, 0.0f) * w0 +
                  fmaxf(acc[mt][nt][1] + bb1, 0.0f) * w1;
            r1 += fmaxf(acc[mt][nt][2] + bb0, 0.0f) * w0 +
                  fmaxf(acc[mt][nt][3] + bb1, 0.0f) * w1;
        }
        r0 += __shfl_xor_sync(0xffffffffu, r0, 1);
        r0 += __shfl_xor_sync(0xffffffffu, r0, 2);
        r1 += __shfl_xor_sync(0xffffffffu, r1, 1);
        r1 += __shfl_xor_sync(0xffffffffu, r1, 2);
        if (qc == 0) {
            atomicAdd(&g_s[m0 + wm + mt * 16 + qr], r0);
            atomicAdd(&g_s[m0 + wm + mt * 16 + qr + 8], r1);
        }
    }
}

// ---------------- softmax + weighted aggregation ----------------
__global__ __launch_bounds__(192) void softmax_agg_kernel(
    const float* __restrict__ X, const int* __restrict__ cidx,
    const int* __restrict__ clen, float* __restrict__ out) {
    __shared__ float sc[LL];
    __shared__ int ix[LL];
    const int c = blockIdx.x;
    const int tid = threadIdx.x;

    if (tid < LL) {
        int len = clen[c];
        int id = cidx[c * LL + tid];
        ix[tid] = id;
        sc[tid] = (tid < len) ? g_s[id] : -INFINITY;
    }
    __syncthreads();

    float mx = -INFINITY;
#pragma unroll
    for (int l = 0; l < LL; l++) mx = fmaxf(mx, sc[l]);
    float p[LL];
    float sum = 0.0f;
#pragma unroll
    for (int l = 0; l < LL; l++) { p[l] = __expf(sc[l] - mx); sum += p[l]; }
    float inv = 1.0f / sum;
#pragma unroll
    for (int l = 0; l < LL; l++) p[l] *= inv;

    const float4* Xv = (const float4*)X;      // row stride DD/4 = 192
    float4 a = make_float4(0.f, 0.f, 0.f, 0.f);
#pragma unroll
    for (int l = 0; l < LL; l++) {
        float4 v = Xv[(size_t)ix[l] * (DD / 4) + tid];
        a.x += p[l] * v.x; a.y += p[l] * v.y;
        a.z += p[l] * v.z; a.w += p[l] * v.w;
    }
    ((float4*)out)[(size_t)c * (DD / 4) + tid] = a;
}

extern "C" void kernel_launch(void* const* d_in, const int* in_sizes, int n_in,
                              void* d_out, int out_size) {
    const float* X    = (const float*)d_in[0];
    const int*   cidx = (const int*)d_in[1];
    const int*   clen = (const int*)d_in[2];
    const float* W1   = (const float*)d_in[3];
    const float* b1   = (const float*)d_in[4];
    const float* Wout = (const float*)d_in[5];
    float* out = (float*)d_out;

    cudaFuncSetAttribute(score_gemm_mma, cudaFuncAttributeMaxDynamicSharedMemorySize,
                         SMEM_TOTAL);

    convert_X_kernel<<<MM * DD / 4 / 256, 256>>>(X);
    convert_W1_kernel<<<dim3(DD / 32, DD / 32), dim3(32, 8)>>>(W1);
    score_gemm_mma<<<dim3(DD / BN, MM / BM), 128, SMEM_TOTAL>>>(b1, Wout);
    softmax_agg_kernel<<<CC, 192>>>(X, cidx, clen, out);
}

// round 7
// speedup vs baseline: 4.1806x; 1.3002x over previous
#include <cuda_runtime.h>
#include <cuda_fp16.h>
#include <cstdint>
#include <math.h>

#define DD 768
#define MM 8192
#define CC 2048
#define LL 16

#define BM 64
#define BN 128
#define BK 32
#define NITER (DD / BK)       // 24
#define NSTAGE 4

// padded smem row: 32 data + 8 pad fp16 = 80B (conflict-free ldmatrix)
#define LDT 40
#define OFF_A 0
#define OFF_B (BM * LDT * 2)                 // 5120
#define STAGE_BYTES (OFF_B + BN * LDT * 2)   // 15360
#define SMEM_TOTAL (NSTAGE * STAGE_BYTES)    // 61440

// ---------------- device globals ----------------
__device__ float g_s[MM];
__device__ __half g_Xh[MM * DD];
__device__ __half g_Bh[DD * DD];   // [n][k] = W1[k][n] (transposed, K-major)

// ---------------- helpers ----------------
__device__ __forceinline__ uint32_t smem_u32(const void* p) {
    uint32_t a;
    asm("{ .reg .u64 t; cvta.to.shared.u64 t, %1; cvt.u32.u64 %0, t; }" : "=r"(a) : "l"(p));
    return a;
}
__device__ __forceinline__ void cp16(uint32_t dst, const void* src) {
    asm volatile("cp.async.cg.shared.global [%0], [%1], 16;" :: "r"(dst), "l"(src));
}
__device__ __forceinline__ void ldsm4(uint32_t* r, uint32_t addr) {
    asm volatile("ldmatrix.sync.aligned.m8n8.x4.shared.b16 {%0,%1,%2,%3}, [%4];"
                 : "=r"(r[0]), "=r"(r[1]), "=r"(r[2]), "=r"(r[3]) : "r"(addr));
}
__device__ __forceinline__ void mma16816(float* c, const uint32_t* a, const uint32_t* b) {
    asm volatile(
        "mma.sync.aligned.m16n8k16.row.col.f32.f16.f16.f32 "
        "{%0,%1,%2,%3}, {%4,%5,%6,%7}, {%8,%9}, {%0,%1,%2,%3};"
        : "+f"(c[0]), "+f"(c[1]), "+f"(c[2]), "+f"(c[3])
        : "r"(a[0]), "r"(a[1]), "r"(a[2]), "r"(a[3]), "r"(b[0]), "r"(b[1]));
}

// ---------------- precompute kernels ----------------
__global__ void convert_X_kernel(const float* __restrict__ X) {
    int i = blockIdx.x * 256 + threadIdx.x;     // over MM*DD/4
    if (i < MM) g_s[i] = 0.0f;                  // fold zero_s in here
    float4 v = ((const float4*)X)[i];
    __half h0 = __float2half_rn(v.x), h1 = __float2half_rn(v.y);
    __half h2 = __float2half_rn(v.z), h3 = __float2half_rn(v.w);
    uint2 ph;
    ph.x = ((uint32_t)*(uint16_t*)&h1 << 16) | *(uint16_t*)&h0;
    ph.y = ((uint32_t)*(uint16_t*)&h3 << 16) | *(uint16_t*)&h2;
    ((uint2*)g_Xh)[i] = ph;
}

__global__ void convert_W1_kernel(const float* __restrict__ W1) {
    __shared__ float t[32][33];
    int n0 = blockIdx.x * 32, k0 = blockIdx.y * 32;
    int tx = threadIdx.x, ty = threadIdx.y;     // (32, 8)
#pragma unroll
    for (int i = 0; i < 32; i += 8)
        t[ty + i][tx] = W1[(size_t)(k0 + ty + i) * DD + n0 + tx];
    __syncthreads();
#pragma unroll
    for (int i = 0; i < 32; i += 8)
        g_Bh[(size_t)(n0 + ty + i) * DD + k0 + tx] = __float2half_rn(t[tx][ty + i]);
}

// ---------------- mma.sync score GEMM ----------------
__device__ __forceinline__ void load_stage(uint32_t base, int k0, int m0, int n0, int tid) {
    int r = tid >> 2;                 // 0..31
    int cb = tid & 3;                 // 16B block (8 fp16) within 64B row
#pragma unroll
    for (int p = 0; p < 2; p++) {     // A: 64 rows
        int row = p * 32 + r;
        uint32_t so = (uint32_t)row * (LDT * 2) + cb * 16;
        cp16(base + OFF_A + so, g_Xh + (size_t)(m0 + row) * DD + k0 + cb * 8);
    }
#pragma unroll
    for (int p = 0; p < 4; p++) {     // B: 128 rows
        int row = p * 32 + r;
        uint32_t so = (uint32_t)row * (LDT * 2) + cb * 16;
        cp16(base + OFF_B + so, g_Bh + (size_t)(n0 + row) * DD + k0 + cb * 8);
    }
    asm volatile("cp.async.commit_group;" ::: "memory");
}

__global__ __launch_bounds__(128, 3) void score_gemm_mma(
    const float* __restrict__ b1, const float* __restrict__ Wout) {
    extern __shared__ char smem[];
    uint32_t sb = smem_u32(smem);
    const int tid = threadIdx.x;
    const int wid = tid >> 5, lane = tid & 31;
    const int wm = (wid >> 1) * 32;           // warp m offset (0/32)
    const int wn = (wid & 1) * 64;            // warp n offset (0/64)
    const int m0 = blockIdx.y * BM, n0 = blockIdx.x * BN;

    float acc[2][8][4];
#pragma unroll
    for (int mt = 0; mt < 2; mt++)
#pragma unroll
        for (int nt = 0; nt < 8; nt++)
#pragma unroll
            for (int c = 0; c < 4; c++) acc[mt][nt][c] = 0.0f;

    // prologue: 3 stages in flight
    load_stage(sb, 0, m0, n0, tid);
    load_stage(sb + STAGE_BYTES, BK, m0, n0, tid);
    load_stage(sb + 2 * STAGE_BYTES, 2 * BK, m0, n0, tid);

    // ldmatrix lane offsets
    const uint32_t aRow = (lane & 15);
    const uint32_t aCol = (lane >> 4) << 3;
    const uint32_t bN   = ((lane >> 4) << 3) + (lane & 7);
    const uint32_t bK   = ((lane >> 3) & 1) << 3;

    for (int it = 0; it < NITER; it++) {
        // exact drain: stages newer than `it` still loading = min(2, NITER-1-it)
        if (it < NITER - 2)       asm volatile("cp.async.wait_group 2;" ::: "memory");
        else if (it == NITER - 2) asm volatile("cp.async.wait_group 1;" ::: "memory");
        else                      asm volatile("cp.async.wait_group 0;" ::: "memory");
        __syncthreads();
        uint32_t st = sb + (it % NSTAGE) * STAGE_BYTES;
        if (it + 3 < NITER)
            load_stage(sb + ((it + 3) % NSTAGE) * STAGE_BYTES, (it + 3) * BK, m0, n0, tid);

        // load all frags for this BK=32 iter, then 32 back-to-back MMAs
        uint32_t Ah[2][2][4], Bh[2][4][4];
#pragma unroll
        for (int h = 0; h < 2; h++) {
            int kk = h * 16;
#pragma unroll
            for (int mt = 0; mt < 2; mt++) {
                uint32_t off = ((wm + mt * 16 + aRow) * LDT + kk + aCol) * 2;
                ldsm4(Ah[h][mt], st + OFF_A + off);
            }
#pragma unroll
            for (int np = 0; np < 4; np++) {
                uint32_t off = ((wn + np * 16 + bN) * LDT + kk + bK) * 2;
                ldsm4(Bh[h][np], st + OFF_B + off);
            }
        }
#pragma unroll
        for (int h = 0; h < 2; h++)
#pragma unroll
            for (int mt = 0; mt < 2; mt++)
#pragma unroll
                for (int np = 0; np < 4; np++) {
                    mma16816(acc[mt][2 * np],     Ah[h][mt], Bh[h][np]);
                    mma16816(acc[mt][2 * np + 1], Ah[h][mt], Bh[h][np] + 2);
                }
    }

    // epilogue: bias + relu + dot(Wout), quad-reduce, atomic per-mention score
    const int qr = lane >> 2;
    const int qc = lane & 3;
#pragma unroll
    for (int mt = 0; mt < 2; mt++) {
        float r0 = 0.0f, r1 = 0.0f;
#pragma unroll
        for (int nt = 0; nt < 8; nt++) {
            int n = n0 + wn + nt * 8 + qc * 2;
            float w0 = Wout[n], w1 = Wout[n + 1];
            float bb0 = b1[n], bb1 = b1[n + 1];
            r0 += fmaxf(acc[mt][nt][0] + bb0, 0.0f) * w0 +
                  fmaxf(acc[mt][nt][1] + bb1, 0.0f) * w1;
            r1 += fmaxf(acc[mt][nt][2] + bb0, 0.0f) * w0 +
                  fmaxf(acc[mt][nt][3] + bb1, 0.0f) * w1;
        }
        r0 += __shfl_xor_sync(0xffffffffu, r0, 1);
        r0 += __shfl_xor_sync(0xffffffffu, r0, 2);
        r1 += __shfl_xor_sync(0xffffffffu, r1, 1);
        r1 += __shfl_xor_sync(0xffffffffu, r1, 2);
        if (qc == 0) {
            atomicAdd(&g_s[m0 + wm + mt * 16 + qr], r0);
            atomicAdd(&g_s[m0 + wm + mt * 16 + qr + 8], r1);
        }
    }
}

// ---------------- softmax + weighted aggregation ----------------
__global__ __launch_bounds__(192) void softmax_agg_kernel(
    const float* __restrict__ X, const int* __restrict__ cidx,
    const int* __restrict__ clen, float* __restrict__ out) {
    __shared__ float sc[LL];
    __shared__ int ix[LL];
    const int c = blockIdx.x;
    const int tid = threadIdx.x;

    if (tid < LL) {
        int len = clen[c];
        int id = cidx[c * LL + tid];
        ix[tid] = id;
        sc[tid] = (tid < len) ? g_s[id] : -INFINITY;
    }
    __syncthreads();

    float mx = -INFINITY;
#pragma unroll
    for (int l = 0; l < LL; l++) mx = fmaxf(mx, sc[l]);
    float p[LL];
    float sum = 0.0f;
#pragma unroll
    for (int l = 0; l < LL; l++) { p[l] = __expf(sc[l] - mx); sum += p[l]; }
    float inv = 1.0f / sum;
#pragma unroll
    for (int l = 0; l < LL; l++) p[l] *= inv;

    const float4* Xv = (const float4*)X;      // row stride DD/4 = 192
    float4 a = make_float4(0.f, 0.f, 0.f, 0.f);
#pragma unroll
    for (int l = 0; l < LL; l++) {
        float4 v = Xv[(size_t)ix[l] * (DD / 4) + tid];
        a.x += p[l] * v.x; a.y += p[l] * v.y;
        a.z += p[l] * v.z; a.w += p[l] * v.w;
    }
    ((float4*)out)[(size_t)c * (DD / 4) + tid] = a;
}

extern "C" void kernel_launch(void* const* d_in, const int* in_sizes, int n_in,
                              void* d_out, int out_size) {
    const float* X    = (const float*)d_in[0];
    const int*   cidx = (const int*)d_in[1];
    const int*   clen = (const int*)d_in[2];
    const float* W1   = (const float*)d_in[3];
    const float* b1   = (const float*)d_in[4];
    const float* Wout = (const float*)d_in[5];
    float* out = (float*)d_out;

    cudaFuncSetAttribute(score_gemm_mma, cudaFuncAttributeMaxDynamicSharedMemorySize,
                         SMEM_TOTAL);

    convert_X_kernel<<<MM * DD / 4 / 256, 256>>>(X);
    convert_W1_kernel<<<dim3(DD / 32, DD / 32), dim3(32, 8)>>>(W1);
    score_gemm_mma<<<dim3(DD / BN, MM / BM), 128, SMEM_TOTAL>>>(b1, Wout);
    softmax_agg_kernel<<<CC, 192>>>(X, cidx, clen, out);
}

// round 8
// speedup vs baseline: 4.2046x; 1.0057x over previous
#include <cuda_runtime.h>
#include <cuda_fp16.h>
#include <cstdint>
#include <math.h>

#define DD 768
#define MM 8192
#define CC 2048
#define LL 16

#define BM 64
#define BN 128
#define BK 32
#define NITER (DD / BK)       // 24
#define NSTAGE 4

// padded smem row: 32 data + 8 pad fp16 = 80B (conflict-free ldmatrix)
#define LDT 40
#define OFF_A 0
#define OFF_B (BM * LDT * 2)                 // 5120
#define STAGE_BYTES (OFF_B + BN * LDT * 2)   // 15360
#define SMEM_TOTAL (NSTAGE * STAGE_BYTES)    // 61440

// ---------------- device globals ----------------
__device__ float g_s[MM];
__device__ __half g_Xh[MM * DD];
__device__ __half g_Bh[DD * DD];   // [n][k] = W1[k][n] (transposed, K-major)

// ---------------- helpers ----------------
__device__ __forceinline__ uint32_t smem_u32(const void* p) {
    uint32_t a;
    asm("{ .reg .u64 t; cvta.to.shared.u64 t, %1; cvt.u32.u64 %0, t; }" : "=r"(a) : "l"(p));
    return a;
}
__device__ __forceinline__ void cp16(uint32_t dst, const void* src) {
    asm volatile("cp.async.cg.shared.global [%0], [%1], 16;" :: "r"(dst), "l"(src));
}
__device__ __forceinline__ void ldsm4(uint32_t* r, uint32_t addr) {
    asm volatile("ldmatrix.sync.aligned.m8n8.x4.shared.b16 {%0,%1,%2,%3}, [%4];"
                 : "=r"(r[0]), "=r"(r[1]), "=r"(r[2]), "=r"(r[3]) : "r"(addr));
}
__device__ __forceinline__ void mma16816(float* c, const uint32_t* a, const uint32_t* b) {
    asm volatile(
        "mma.sync.aligned.m16n8k16.row.col.f32.f16.f16.f32 "
        "{%0,%1,%2,%3}, {%4,%5,%6,%7}, {%8,%9}, {%0,%1,%2,%3};"
        : "+f"(c[0]), "+f"(c[1]), "+f"(c[2]), "+f"(c[3])
        : "r"(a[0]), "r"(a[1]), "r"(a[2]), "r"(a[3]), "r"(b[0]), "r"(b[1]));
}

// ---------------- precompute kernels ----------------
__global__ void convert_X_kernel(const float* __restrict__ X) {
    int i = blockIdx.x * 256 + threadIdx.x;     // over MM*DD/4
    if (i < MM) g_s[i] = 0.0f;                  // fold zero_s in here
    float4 v = ((const float4*)X)[i];
    __half h0 = __float2half_rn(v.x), h1 = __float2half_rn(v.y);
    __half h2 = __float2half_rn(v.z), h3 = __float2half_rn(v.w);
    uint2 ph;
    ph.x = ((uint32_t)*(uint16_t*)&h1 << 16) | *(uint16_t*)&h0;
    ph.y = ((uint32_t)*(uint16_t*)&h3 << 16) | *(uint16_t*)&h2;
    ((uint2*)g_Xh)[i] = ph;
}

__global__ void convert_W1_kernel(const float* __restrict__ W1) {
    __shared__ float t[32][33];
    int n0 = blockIdx.x * 32, k0 = blockIdx.y * 32;
    int tx = threadIdx.x, ty = threadIdx.y;     // (32, 8)
#pragma unroll
    for (int i = 0; i < 32; i += 8)
        t[ty + i][tx] = W1[(size_t)(k0 + ty + i) * DD + n0 + tx];
    __syncthreads();
#pragma unroll
    for (int i = 0; i < 32; i += 8)
        g_Bh[(size_t)(n0 + ty + i) * DD + k0 + tx] = __float2half_rn(t[tx][ty + i]);
}

// ---------------- mma.sync score GEMM ----------------
__device__ __forceinline__ void load_stage(uint32_t base, int k0, int m0, int n0, int tid) {
    int r = tid >> 2;                 // 0..31
    int cb = tid & 3;                 // 16B block (8 fp16) within 64B row
#pragma unroll
    for (int p = 0; p < 2; p++) {     // A: 64 rows
        int row = p * 32 + r;
        uint32_t so = (uint32_t)row * (LDT * 2) + cb * 16;
        cp16(base + OFF_A + so, g_Xh + (size_t)(m0 + row) * DD + k0 + cb * 8);
    }
#pragma unroll
    for (int p = 0; p < 4; p++) {     // B: 128 rows
        int row = p * 32 + r;
        uint32_t so = (uint32_t)row * (LDT * 2) + cb * 16;
        cp16(base + OFF_B + so, g_Bh + (size_t)(n0 + row) * DD + k0 + cb * 8);
    }
    asm volatile("cp.async.commit_group;" ::: "memory");
}

__global__ __launch_bounds__(128, 3) void score_gemm_mma(
    const float* __restrict__ b1, const float* __restrict__ Wout) {
    extern __shared__ char smem[];
    uint32_t sb = smem_u32(smem);
    const int tid = threadIdx.x;
    const int wid = tid >> 5, lane = tid & 31;
    const int wm = (wid >> 1) * 32;           // warp m offset (0/32)
    const int wn = (wid & 1) * 64;            // warp n offset (0/64)
    const int m0 = blockIdx.y * BM, n0 = blockIdx.x * BN;

    float acc[2][8][4];
#pragma unroll
    for (int mt = 0; mt < 2; mt++)
#pragma unroll
        for (int nt = 0; nt < 8; nt++)
#pragma unroll
            for (int c = 0; c < 4; c++) acc[mt][nt][c] = 0.0f;

    // prologue: 3 stages in flight
    load_stage(sb, 0, m0, n0, tid);
    load_stage(sb + STAGE_BYTES, BK, m0, n0, tid);
    load_stage(sb + 2 * STAGE_BYTES, 2 * BK, m0, n0, tid);

    // ldmatrix lane offsets
    const uint32_t aRow = (lane & 15);
    const uint32_t aCol = (lane >> 4) << 3;
    const uint32_t bN   = ((lane >> 4) << 3) + (lane & 7);
    const uint32_t bK   = ((lane >> 3) & 1) << 3;

    for (int it = 0; it < NITER; it++) {
        // exact drain: stages newer than `it` still loading = min(2, NITER-1-it)
        if (it < NITER - 2)       asm volatile("cp.async.wait_group 2;" ::: "memory");
        else if (it == NITER - 2) asm volatile("cp.async.wait_group 1;" ::: "memory");
        else                      asm volatile("cp.async.wait_group 0;" ::: "memory");
        __syncthreads();
        uint32_t st = sb + (it % NSTAGE) * STAGE_BYTES;
        if (it + 3 < NITER)
            load_stage(sb + ((it + 3) % NSTAGE) * STAGE_BYTES, (it + 3) * BK, m0, n0, tid);

        // load all frags for this BK=32 iter, then 32 back-to-back MMAs
        uint32_t Ah[2][2][4], Bh[2][4][4];
#pragma unroll
        for (int h = 0; h < 2; h++) {
            int kk = h * 16;
#pragma unroll
            for (int mt = 0; mt < 2; mt++) {
                uint32_t off = ((wm + mt * 16 + aRow) * LDT + kk + aCol) * 2;
                ldsm4(Ah[h][mt], st + OFF_A + off);
            }
#pragma unroll
            for (int np = 0; np < 4; np++) {
                uint32_t off = ((wn + np * 16 + bN) * LDT + kk + bK) * 2;
                ldsm4(Bh[h][np], st + OFF_B + off);
            }
        }
#pragma unroll
        for (int h = 0; h < 2; h++)
#pragma unroll
            for (int mt = 0; mt < 2; mt++)
#pragma unroll
                for (int np = 0; np < 4; np++) {
                    mma16816(acc[mt][2 * np],     Ah[h][mt], Bh[h][np]);
                    mma16816(acc[mt][2 * np + 1], Ah[h][mt], Bh[h][np] + 2);
                }
    }

    // epilogue: bias + relu + dot(Wout), quad-reduce, atomic per-mention score
    const int qr = lane >> 2;
    const int qc = lane & 3;
#pragma unroll
    for (int mt = 0; mt < 2; mt++) {
        float r0 = 0.0f, r1 = 0.0f;
#pragma unroll
        for (int nt = 0; nt < 8; nt++) {
            int n = n0 + wn + nt * 8 + qc * 2;
            float w0 = Wout[n], w1 = Wout[n + 1];
            float bb0 = b1[n], bb1 = b1[n + 1];
            r0 += fmaxf(acc[mt][nt][0] + bb0, 0.0f) * w0 +
                  fmaxf(acc[mt][nt][1] + bb1, 0.0f) * w1;
            r1 += fmaxf(acc[mt][nt][2] + bb0, 0.0f) * w0 +
                  fmaxf(acc[mt][nt][3] + bb1, 0.0f) * w1;
        }
        r0 += __shfl_xor_sync(0xffffffffu, r0, 1);
        r0 += __shfl_xor_sync(0xffffffffu, r0, 2);
        r1 += __shfl_xor_sync(0xffffffffu, r1, 1);
        r1 += __shfl_xor_sync(0xffffffffu, r1, 2);
        if (qc == 0) {
            atomicAdd(&g_s[m0 + wm + mt * 16 + qr], r0);
            atomicAdd(&g_s[m0 + wm + mt * 16 + qr + 8], r1);
        }
    }
}

// ---------------- softmax + weighted aggregation (fp16 gather) ----------------
__global__ __launch_bounds__(192) void softmax_agg_kernel(
    const int* __restrict__ cidx, const int* __restrict__ clen,
    float* __restrict__ out) {
    __shared__ float sc[LL];
    __shared__ int ix[LL];
    const int c = blockIdx.x;
    const int tid = threadIdx.x;

    if (tid < LL) {
        int len = clen[c];
        int id = cidx[c * LL + tid];
        ix[tid] = id;
        sc[tid] = (tid < len) ? g_s[id] : -INFINITY;
    }
    __syncthreads();

    float mx = -INFINITY;
#pragma unroll
    for (int l = 0; l < LL; l++) mx = fmaxf(mx, sc[l]);
    float p[LL];
    float sum = 0.0f;
#pragma unroll
    for (int l = 0; l < LL; l++) { p[l] = __expf(sc[l] - mx); sum += p[l]; }
    float inv = 1.0f / sum;
#pragma unroll
    for (int l = 0; l < LL; l++) p[l] *= inv;

    // gather fp16 rows (half the L2 traffic of fp32), accumulate fp32
    const __half2* Xv = (const __half2*)g_Xh;   // row stride DD/2 = 384 half2
    float4 a = make_float4(0.f, 0.f, 0.f, 0.f);
#pragma unroll
    for (int l = 0; l < LL; l++) {
        size_t base = (size_t)ix[l] * (DD / 2) + tid * 2;
        __half2 v0 = Xv[base];
        __half2 v1 = Xv[base + 1];
        float2 f0 = __half22float2(v0);
        float2 f1 = __half22float2(v1);
        a.x += p[l] * f0.x; a.y += p[l] * f0.y;
        a.z += p[l] * f1.x; a.w += p[l] * f1.y;
    }
    ((float4*)out)[(size_t)c * (DD / 4) + tid] = a;
}

extern "C" void kernel_launch(void* const* d_in, const int* in_sizes, int n_in,
                              void* d_out, int out_size) {
    const float* X    = (const float*)d_in[0];
    const int*   cidx = (const int*)d_in[1];
    const int*   clen = (const int*)d_in[2];
    const float* W1   = (const float*)d_in[3];
    const float* b1   = (const float*)d_in[4];
    const float* Wout = (const float*)d_in[5];
    float* out = (float*)d_out;

    cudaFuncSetAttribute(score_gemm_mma, cudaFuncAttributeMaxDynamicSharedMemorySize,
                         SMEM_TOTAL);

    convert_X_kernel<<<MM * DD / 4 / 256, 256>>>(X);
    convert_W1_kernel<<<dim3(DD / 32, DD / 32), dim3(32, 8)>>>(W1);
    score_gemm_mma<<<dim3(DD / BN, MM / BM), 128, SMEM_TOTAL>>>(b1, Wout);
    softmax_agg_kernel<<<CC, 192>>>(cidx, clen, out);
}